// round 13
// baseline (speedup 1.0000x reference)
#include <cuda_runtime.h>

namespace {

constexpr int NQ     = 12;
constexpr int DIM    = 4096;
constexpr int LAYERS = 8;
constexpr int FEAT   = 3072;
constexpr int NCLASS = 10;
constexpr int WARPS  = 7;            // warps per CTA, each warp = 2 states
constexpr int TPB    = WARPS * 32;

using u64 = unsigned long long;

__device__ __forceinline__ u64 pack2(float lo, float hi) {
    u64 r; asm("mov.b64 %0, {%1, %2};" : "=l"(r) : "f"(lo), "f"(hi)); return r;
}
__device__ __forceinline__ void unpack2(u64 v, float& lo, float& hi) {
    asm("mov.b64 {%0, %1}, %2;" : "=f"(lo), "=f"(hi) : "l"(v));
}
__device__ __forceinline__ u64 mul2(u64 a, u64 b) {
    u64 r; asm("mul.rn.f32x2 %0, %1, %2;" : "=l"(r) : "l"(a), "l"(b)); return r;
}
__device__ __forceinline__ u64 add2(u64 a, u64 b) {
    u64 r; asm("add.rn.f32x2 %0, %1, %2;" : "=l"(r) : "l"(a), "l"(b)); return r;
}
__device__ __forceinline__ u64 fma2(u64 a, u64 b, u64 c) {
    u64 r; asm("fma.rn.f32x2 %0, %1, %2, %3;" : "=l"(r) : "l"(a), "l"(b), "l"(c)); return r;
}

// One WARP owns one job = 2 batch states packed as f32x2 in a private 32KB
// smem slab. No __syncthreads in the main loop.
//
// Amplitude i (12 bits): row = i&31 (bits 0-4), col = i>>5 (bits 5-11).
// Physical slot (u64 units): phys(row, col) = row*128 + (col ^ row).
// Qubit q acts on bit p = 11-q; per-layer CNOT chain = Gray map j = i^(i>>1).
// Tan-form butterflies; cos products and L2 norm folded into epilogue scale.
//
// Layer = 3 hazard-free passes:
//  P1: lane owns one column per chunk: gates bits 0-4 (regs) + 5-7 (shfl);
//      read/write own column only.
//  P2a: lane owns its row: regs k = col bits 3-6 (16 cols per xl = col bits
//      0-2): gates bits 8-11; write back to the SAME locations (identity).
//  P2b: Gray permutation, grouped by h = col bits 4-6. Group map = Gray3(h):
//      cycles (0)(1)(2 3)(4 6 5 7). Self groups: read->syncwarp->write.
//      (2,3): joint read then write. 4-cycle: hold grp4 in regs, chain
//      7->4, 5->7, 6->5, 4->6, with syncwarps so every group is fully read
//      before any lane writes into it.

__device__ __forceinline__ void p2b_load(const u64* buf, int lane, int h, u64* a) {
    #pragma unroll
    for (int k = 0; k < 16; k++) {
        const int col = (h << 4) | k;
        a[k] = buf[lane * 128 + (col ^ lane)];
    }
}
__device__ __forceinline__ void p2b_store(u64* buf, int lane, int grayl, int h, const u64* a) {
    #pragma unroll
    for (int k = 0; k < 16; k++) {
        const int col  = (h << 4) | k;
        const int jrow = grayl ^ ((k & 1) << 4);
        const int jcol = col ^ (col >> 1);
        buf[jrow * 128 + (jcol ^ jrow)] = a[k];
    }
}

__global__ void __launch_bounds__(TPB, 1) qnn_kernel(
    const float* __restrict__ x,       // [B, 3072]
    const float* __restrict__ angles,  // [8, 12]
    const float* __restrict__ Wm,      // [10, 4096]
    const float* __restrict__ bias,    // [10]
    float* __restrict__ out,           // [B, 10]
    int njobs)
{
    extern __shared__ unsigned char smraw[];
    float* s_t = reinterpret_cast<float*>(smraw);        // 96 tan values
    float* s_c = s_t + LAYERS * NQ;                      // 96 cos values
    u64*   bufall = reinterpret_cast<u64*>(smraw + 1024);

    const int t    = threadIdx.x;
    const int lane = t & 31;
    const int wid  = t >> 5;

    if (t < LAYERS * NQ) {
        const int l = t / NQ;
        const int q = t - l * NQ;
        const float a = angles[t];
        const int p = NQ - 1 - q;            // qubit q -> bit position p
        const float c = cosf(a);
        s_t[l * NQ + p] = sinf(a) / c;
        s_c[t] = c;
    }
    __syncthreads();   // the only block-wide barrier

    const int job = blockIdx.x * WARPS + wid;
    if (job >= njobs) return;

    u64* buf = bufall + wid * DIM;           // this warp's 4096-u64 slab

    // global cos product over all 96 gates
    float ctot = s_c[lane] * s_c[lane + 32] * s_c[lane + 64];
    #pragma unroll
    for (int o = 16; o > 0; o >>= 1)
        ctot *= __shfl_xor_sync(0xffffffffu, ctot, o);

    // ---- load 2 input rows, pack, accumulate ssq, store swizzled ----
    const float* x0 = x + (size_t)(2 * job)     * FEAT;
    const float* x1 = x + (size_t)(2 * job + 1) * FEAT;
    u64 ssq = 0ull;
    #pragma unroll 1
    for (int m = 0; m < 128; m++) {
        u64 val = 0ull;
        if (m < FEAT / 32) {                  // m < 96
            val = pack2(x0[m * 32 + lane], x1[m * 32 + lane]);
            ssq = fma2(val, val, ssq);
        }
        buf[lane * 128 + (m ^ lane)] = val;   // (row=lane, col=m)
    }
    #pragma unroll
    for (int o = 16; o > 0; o >>= 1)
        ssq = add2(ssq, __shfl_xor_sync(0xffffffffu, ssq, o));
    __syncwarp();

    const int grayl = lane ^ (lane >> 1);     // 5-bit Gray of lane

    #pragma unroll 1
    for (int l = 0; l < LAYERS; l++) {
        const float* tl = s_t + l * NQ;

        // ================= Pass 1: bits 0-4 regs, 5-7 shfl ================
        #pragma unroll 1
        for (int c = 0; c < 4; c++) {
            const int col = c * 32 + lane;    // this lane's private column
            u64 v[32];
            #pragma unroll
            for (int r = 0; r < 32; r++) v[r] = buf[r * 128 + (col ^ r)];

            #pragma unroll
            for (int p = 0; p < 5; p++) {
                const float tg = tl[p];
                const u64 tg2 = pack2(tg, tg), ntg2 = pack2(-tg, -tg);
                const int m = 1 << p;
                #pragma unroll
                for (int lo = 0; lo < 32; lo += 2 * m)
                    #pragma unroll
                    for (int k = 0; k < m; k++) {
                        const int r0 = lo + k, r1 = r0 + m;
                        const u64 a0 = v[r0], a1 = v[r1];
                        v[r0] = fma2(ntg2, a1, a0);
                        v[r1] = fma2(tg2,  a0, a1);
                    }
            }
            #pragma unroll
            for (int p = 5; p < 8; p++) {
                const float tg = tl[p];
                const int mask = 1 << (p - 5);
                const float se = (lane & mask) ? tg : -tg;
                const u64 se2 = pack2(se, se);
                #pragma unroll
                for (int r = 0; r < 32; r++) {
                    const u64 pr = __shfl_xor_sync(0xffffffffu, v[r], mask);
                    v[r] = fma2(se2, pr, v[r]);
                }
            }
            #pragma unroll
            for (int r = 0; r < 32; r++) buf[r * 128 + (col ^ r)] = v[r];
        }
        __syncwarp();

        // ====== Pass 2a: bits 8-11 in regs, identity write-back ==========
        #pragma unroll 1
        for (int xl = 0; xl < 8; xl++) {
            u64 w[16];
            #pragma unroll
            for (int k = 0; k < 16; k++)
                w[k] = buf[lane * 128 + (((k << 3) | xl) ^ lane)];

            #pragma unroll
            for (int p = 0; p < 4; p++) {
                const float tg = tl[8 + p];
                const u64 tg2 = pack2(tg, tg), ntg2 = pack2(-tg, -tg);
                const int m = 1 << p;
                #pragma unroll
                for (int lo = 0; lo < 16; lo += 2 * m)
                    #pragma unroll
                    for (int k = 0; k < m; k++) {
                        const int r0 = lo + k, r1 = r0 + m;
                        const u64 a0 = w[r0], a1 = w[r1];
                        w[r0] = fma2(ntg2, a1, a0);
                        w[r1] = fma2(tg2,  a0, a1);
                    }
            }
            #pragma unroll
            for (int k = 0; k < 16; k++)
                buf[lane * 128 + (((k << 3) | xl) ^ lane)] = w[k];
        }
        __syncwarp();

        // ====== Pass 2b: Gray permutation j = i ^ (i>>1) ==================
        {
            u64 a[16], b[16];
            // group 0 (self)
            p2b_load(buf, lane, 0, a);
            __syncwarp();
            p2b_store(buf, lane, grayl, 0, a);
            __syncwarp();
            // group 1 (self)
            p2b_load(buf, lane, 1, a);
            __syncwarp();
            p2b_store(buf, lane, grayl, 1, a);
            __syncwarp();
            // groups 2,3 (swap)
            p2b_load(buf, lane, 2, a);
            p2b_load(buf, lane, 3, b);
            __syncwarp();
            p2b_store(buf, lane, grayl, 2, a);   // -> group 3 (read)
            p2b_store(buf, lane, grayl, 3, b);   // -> group 2 (read)
            __syncwarp();
            // 4-cycle: 4->6, 6->5, 5->7, 7->4
            p2b_load(buf, lane, 4, a);
            p2b_load(buf, lane, 7, b);
            __syncwarp();                        // groups 4 and 7 fully read
            p2b_store(buf, lane, grayl, 7, b);   // -> group 4 (read)
            p2b_load(buf, lane, 5, b);
            __syncwarp();                        // group 5 fully read
            p2b_store(buf, lane, grayl, 5, b);   // -> group 7 (read)
            p2b_load(buf, lane, 6, b);
            __syncwarp();                        // group 6 fully read
            p2b_store(buf, lane, grayl, 6, b);   // -> group 5 (read)
            p2b_store(buf, lane, grayl, 4, a);   // -> group 6 (read)
            __syncwarp();
        }
    }

    // ---- epilogue: probs . W^T, scaled by ctot^2/ssq ----
    u64 acc[NCLASS];
    #pragma unroll
    for (int k = 0; k < NCLASS; k++) acc[k] = 0ull;
    #pragma unroll 1
    for (int m = 0; m < 128; m++) {
        const u64 pv = buf[lane * 128 + (m ^ lane)];
        const u64 p2 = mul2(pv, pv);
        const int i = m * 32 + lane;
        #pragma unroll
        for (int k = 0; k < NCLASS; k++) {
            const float wv = Wm[k * DIM + i];
            acc[k] = fma2(p2, pack2(wv, wv), acc[k]);
        }
    }
    #pragma unroll
    for (int k = 0; k < NCLASS; k++)
        #pragma unroll
        for (int o = 16; o > 0; o >>= 1)
            acc[k] = add2(acc[k], __shfl_xor_sync(0xffffffffu, acc[k], o));

    float n0, n1; unpack2(ssq, n0, n1);
    const float cc = ctot * ctot;
    if (lane < NCLASS) {
        float a0, a1; unpack2(acc[lane], a0, a1);
        out[(size_t)(2 * job) * NCLASS + lane] = a0 * (cc / n0) + bias[lane];
    } else if (lane < 2 * NCLASS) {
        float a0, a1; unpack2(acc[lane - NCLASS], a0, a1);
        out[(size_t)(2 * job + 1) * NCLASS + (lane - NCLASS)]
            = a1 * (cc / n1) + bias[lane - NCLASS];
    }
}

} // namespace

extern "C" void kernel_launch(void* const* d_in, const int* in_sizes, int n_in,
                              void* d_out, int out_size) {
    const float* x      = (const float*)d_in[0];
    const float* angles = (const float*)d_in[1];
    const float* W      = (const float*)d_in[2];
    const float* bias   = (const float*)d_in[3];
    const int batch = in_sizes[0] / FEAT;          // 2048
    const int njobs = batch / 2;                   // 1024 warp-jobs
    const int grid  = (njobs + WARPS - 1) / WARPS; // 147

    const size_t smem = 1024 + (size_t)WARPS * DIM * sizeof(u64);  // 230400 B
    cudaFuncSetAttribute(qnn_kernel,
                         cudaFuncAttributeMaxDynamicSharedMemorySize,
                         (int)smem);
    qnn_kernel<<<grid, TPB, smem>>>(x, angles, W, bias, (float*)d_out, njobs);
}

// round 15
// speedup vs baseline: 1.3324x; 1.3324x over previous
#include <cuda_runtime.h>

namespace {

constexpr int NQ     = 12;
constexpr int DIM    = 4096;
constexpr int LAYERS = 8;
constexpr int FEAT   = 3072;
constexpr int NCLASS = 10;
constexpr int TPB    = 128;    // 4 warps per CTA, ONE state per WARP

// ---------------------------------------------------------------------------
// Virtual-permutation algebra.
// Reference CNOT chain per layer == Gray map j = G i, (G i)_k = i_k ^ i_{k+1}.
// We NEVER move data. After l layers the physical slot s holds logical index
// G^l s. A gate on logical bit p at layer l is an XOR butterfly on physical
// indices with:
//   pair mask  m  = G^{-l} e_p        (G^{-1} col b = bits 0..b)
//   sign mask  sm = row_p(G^l) = (G^T)^l e_p   (G^T col b = bits b, b+1)
// Elementwise tan-form: v[s] += sigma(s)*t*v[s^m], sigma = parity(s&sm)? + : -
// (cos factors folded into one global scalar, applied in the epilogue).
// Final basis map G^8 = I + S^8 (binomials mod 2): j = s ^ (s>>8).
// ---------------------------------------------------------------------------

__host__ __device__ constexpr int gate_m(int l, int p) {   // (G^{-1})^l e_p
    int v = 1 << p;
    for (int it = 0; it < l; it++) {
        int r = 0;
        for (int b = 0; b < 12; b++)
            if ((v >> b) & 1) r ^= (2 << b) - 1;   // G^{-1} col b
        v = r;
    }
    return v;
}
__host__ __device__ constexpr int gate_sm(int l, int p) {  // (G^T)^l e_p
    int v = 1 << p;
    for (int it = 0; it < l; it++) {
        int r = 0;
        for (int b = 0; b < 12; b++)
            if ((v >> b) & 1) r ^= ((1 << b) | (1 << (b + 1))) & 0xFFF;
        v = r;
    }
    return v;
}

// State layout: physical index s = (lane << 7) | r,  r = register 0..127.
// Gates with pair mask in bits 0-6 stay register-local; lane-bit components
// use shfl_xor.

template<int L, int P>
__device__ __forceinline__ void do_gate(float (&v)[128], float t, int lane) {
    constexpr int m     = gate_m(L, P);
    constexpr int regm  = m & 127;
    constexpr int lanem = (m >> 7) & 31;
    constexpr int sm    = gate_sm(L, P);
    constexpr int smlo  = sm & 127;
    constexpr int smhi  = (sm >> 7) & 31;

    // coefficient(lane, r) = (parity(lane&smhi) ^ parity(r&smlo)) ? +t : -t
    const float ls = (__popc(lane & smhi) & 1) ? t : -t;

    if constexpr (lanem == 0) {
        #pragma unroll
        for (int r0 = 0; r0 < 128; r0++) {
            if ((r0 ^ regm) > r0) {
                const int r1 = r0 ^ regm;
                const float c0 = (__popc(r0 & smlo) & 1) ? -ls : ls;
                const float c1 = (__popc(r1 & smlo) & 1) ? -ls : ls;
                const float t0 = v[r0];
                v[r0] = fmaf(c0, v[r1], v[r0]);
                v[r1] = fmaf(c1, t0, v[r1]);
            }
        }
    } else {
        #pragma unroll
        for (int r0 = 0; r0 < 128; r0++) {
            const int r1 = r0 ^ regm;
            if (r1 > r0) {
                const float p0 = __shfl_xor_sync(0xffffffffu, v[r1], lanem);
                const float p1 = __shfl_xor_sync(0xffffffffu, v[r0], lanem);
                const float c0 = (__popc(r0 & smlo) & 1) ? -ls : ls;
                const float c1 = (__popc(r1 & smlo) & 1) ? -ls : ls;
                v[r0] = fmaf(c0, p0, v[r0]);
                v[r1] = fmaf(c1, p1, v[r1]);
            } else if (r1 == r0) {           // pure lane-bit pair
                const float p0 = __shfl_xor_sync(0xffffffffu, v[r0], lanem);
                const float c0 = (__popc(r0 & smlo) & 1) ? -ls : ls;
                v[r0] = fmaf(c0, p0, v[r0]);
            }
        }
    }
}

template<int L, int P>
__device__ __forceinline__ void gates(float (&v)[128], const float* st, int lane) {
    do_gate<L, P>(v, st[L * NQ + P], lane);
    if constexpr (P + 1 < NQ) gates<L, P + 1>(v, st, lane);
}
template<int L>
__device__ __forceinline__ void layers(float (&v)[128], const float* st, int lane) {
    gates<L, 0>(v, st, lane);
    if constexpr (L + 1 < LAYERS) layers<L + 1>(v, st, lane);
}

__global__ void __launch_bounds__(TPB) qnn_kernel(
    const float* __restrict__ x,       // [B, 3072]
    const float* __restrict__ angles,  // [8, 12]
    const float* __restrict__ Wm,      // [10, 4096]
    const float* __restrict__ bias,    // [10]
    float* __restrict__ out)           // [B, 10]
{
    __shared__ float s_tan[LAYERS * NQ];   // tan per [layer][bit position]

    const int t    = threadIdx.x;
    const int lane = t & 31;
    const int wid  = t >> 5;

    if (t < LAYERS * NQ) {
        const int l = t / NQ;
        const int q = t - l * NQ;
        s_tan[l * NQ + (NQ - 1 - q)] = tanf(angles[t]);  // qubit q -> bit 11-q
    }
    __syncthreads();

    const int job = blockIdx.x * (TPB / 32) + wid;   // one state per warp

    // global cos product over all 96 gates (per warp)
    float ctot = cosf(angles[lane]) * cosf(angles[lane + 32]) * cosf(angles[lane + 64]);
    #pragma unroll
    for (int o = 16; o > 0; o >>= 1)
        ctot *= __shfl_xor_sync(0xffffffffu, ctot, o);

    // ---- load state: slot s = (lane<<7)|r = feature index (pad to 4096) ----
    float v[128];
    if (lane < FEAT / 128) {   // lanes 0..23 hold data
        const float4* x4 = reinterpret_cast<const float4*>(
            x + (size_t)job * FEAT + (lane << 7));
        #pragma unroll
        for (int u = 0; u < 32; u++) {
            const float4 w = x4[u];
            v[4*u+0] = w.x; v[4*u+1] = w.y; v[4*u+2] = w.z; v[4*u+3] = w.w;
        }
    } else {
        #pragma unroll
        for (int r = 0; r < 128; r++) v[r] = 0.0f;
    }

    // sum of squares (norm folded into the epilogue scale)
    float ssq = 0.0f;
    #pragma unroll
    for (int r = 0; r < 128; r++) ssq = fmaf(v[r], v[r], ssq);
    #pragma unroll
    for (int o = 16; o > 0; o >>= 1) ssq += __shfl_xor_sync(0xffffffffu, ssq, o);

    // ---- all 96 gates: pure FFMA + SHFL, no smem, no barriers ----
    layers<0>(v, s_tan, lane);

    // ---- probabilities ----
    #pragma unroll
    for (int r = 0; r < 128; r++) v[r] *= v[r];

    // ---- fold final basis map j = s ^ (s>>8): p'[r] = p[r ^ (lane>>1)] ----
    #pragma unroll
    for (int b = 0; b < 4; b++) {
        const bool sw = (lane >> (b + 1)) & 1;
        #pragma unroll
        for (int r0 = 0; r0 < 128; r0++)
            if (!(r0 & (1 << b))) {
                const int r1 = r0 | (1 << b);
                const float a = v[r0], c = v[r1];
                v[r0] = sw ? c : a;
                v[r1] = sw ? a : c;
            }
    }

    // ---- readout: out[k] = scale * sum_j p'[j] W[k][j] + b[k] ----
    const float scale = (ctot * ctot) / ssq;
    float myout = 0.0f;
    #pragma unroll 1
    for (int k = 0; k < NCLASS; k++) {
        const float4* w4 = reinterpret_cast<const float4*>(
            Wm + (size_t)k * DIM + (lane << 7));
        float acc = 0.0f;
        #pragma unroll
        for (int u = 0; u < 32; u++) {
            const float4 w = w4[u];
            acc = fmaf(v[4*u+0], w.x, acc);
            acc = fmaf(v[4*u+1], w.y, acc);
            acc = fmaf(v[4*u+2], w.z, acc);
            acc = fmaf(v[4*u+3], w.w, acc);
        }
        #pragma unroll
        for (int o = 16; o > 0; o >>= 1) acc += __shfl_xor_sync(0xffffffffu, acc, o);
        if (lane == k) myout = acc;
    }
    if (lane < NCLASS)
        out[(size_t)job * NCLASS + lane] = myout * scale + bias[lane];
}

} // namespace

extern "C" void kernel_launch(void* const* d_in, const int* in_sizes, int n_in,
                              void* d_out, int out_size) {
    const float* x      = (const float*)d_in[0];
    const float* angles = (const float*)d_in[1];
    const float* W      = (const float*)d_in[2];
    const float* bias   = (const float*)d_in[3];
    const int batch = in_sizes[0] / FEAT;            // 2048 states
    const int grid  = batch / (TPB / 32);            // 512 CTAs (4 warps each)
    qnn_kernel<<<grid, TPB>>>(x, angles, W, bias, (float*)d_out);
}

// round 16
// speedup vs baseline: 2.0652x; 1.5500x over previous
#include <cuda_runtime.h>

namespace {

constexpr int NQ     = 12;
constexpr int DIM    = 4096;
constexpr int LAYERS = 8;
constexpr int FEAT   = 3072;
constexpr int NCLASS = 10;
constexpr int TPB    = 128;    // 4 warps per CTA = 2 states (2 warps/state)

// ---------------------------------------------------------------------------
// Virtual-permutation algebra (validated in round 15, rel_err 1e-6):
// CNOT chain per layer == Gray map j = G i. Data never moves; a gate on
// logical bit p at layer l is an XOR butterfly on physical indices with
//   pair mask  m  = G^{-l} e_p   (lower-triangular: m is within bits 0..p)
//   sign mask  sm = (G^T)^l e_p
//   v[s] += (parity(s&sm) ? +t : -t) * v[s^m]      (tan form)
// Final basis map G^8: j = s ^ (s>>8). cos factors + L2 norm folded into
// one epilogue scalar.
//
// Physical layout: s = (warp_bit<<11) | (lane<<6) | reg, 64 floats/thread.
// Lower-triangularity => p<=5: register-only; p=6..10: +shfl; p=11 (only):
// cross-warp via one padded smem swap (the single smem use in the loop).
// ---------------------------------------------------------------------------

__host__ __device__ constexpr int gate_m(int l, int p) {   // (G^{-1})^l e_p
    int v = 1 << p;
    for (int it = 0; it < l; it++) {
        int r = 0;
        for (int b = 0; b < 12; b++)
            if ((v >> b) & 1) r ^= (2 << b) - 1;
        v = r;
    }
    return v;
}
__host__ __device__ constexpr int gate_sm(int l, int p) {  // (G^T)^l e_p
    int v = 1 << p;
    for (int it = 0; it < l; it++) {
        int r = 0;
        for (int b = 0; b < 12; b++)
            if ((v >> b) & 1) r ^= ((1 << b) | (1 << (b + 1))) & 0xFFF;
        v = r;
    }
    return v;
}

template<int L, int P>
__device__ __forceinline__ void do_gate(float (&v)[64], float t,
                                        int lane, int wb, int tis, float* sb) {
    constexpr int m      = gate_m(L, P);
    constexpr int regm   = m & 63;
    constexpr int lanem  = (m >> 6) & 31;
    constexpr int wbm    = (m >> 11) & 1;
    constexpr int sm     = gate_sm(L, P);
    constexpr int smlo   = sm & 63;
    constexpr int smlane = (sm >> 6) & 31;
    constexpr int smwb   = (sm >> 11) & 1;

    // c(s) = parity(s & sm) ? +t : -t ; ls carries the lane/warp-bit part.
    const float ls = ((__popc(lane & smlane) ^ (wb & smwb)) & 1) ? t : -t;

    if constexpr (wbm == 1) {
        // cross-warp gate (only p = 11): padded smem swap within the state
        #pragma unroll
        for (int r = 0; r < 64; r++) sb[tis * 65 + r] = v[r];
        __syncthreads();
        const int pt = tis ^ 32 ^ lanem;     // partner thread-in-state
        #pragma unroll
        for (int r = 0; r < 64; r++) {
            const float pv = sb[pt * 65 + (r ^ regm)];
            const float c  = (__popc(r & smlo) & 1) ? -ls : ls;
            v[r] = fmaf(c, pv, v[r]);
        }
        __syncthreads();
    } else if constexpr (lanem != 0) {
        #pragma unroll
        for (int r0 = 0; r0 < 64; r0++) {
            const int r1 = r0 ^ regm;
            if (r1 > r0) {
                const float p0 = __shfl_xor_sync(0xffffffffu, v[r1], lanem);
                const float p1 = __shfl_xor_sync(0xffffffffu, v[r0], lanem);
                const float c0 = (__popc(r0 & smlo) & 1) ? -ls : ls;
                const float c1 = (__popc(r1 & smlo) & 1) ? -ls : ls;
                v[r0] = fmaf(c0, p0, v[r0]);
                v[r1] = fmaf(c1, p1, v[r1]);
            } else if (r1 == r0) {
                const float p0 = __shfl_xor_sync(0xffffffffu, v[r0], lanem);
                const float c0 = (__popc(r0 & smlo) & 1) ? -ls : ls;
                v[r0] = fmaf(c0, p0, v[r0]);
            }
        }
    } else {
        #pragma unroll
        for (int r0 = 0; r0 < 64; r0++) {
            const int r1 = r0 ^ regm;
            if (r1 > r0) {
                const float c0 = (__popc(r0 & smlo) & 1) ? -ls : ls;
                const float c1 = (__popc(r1 & smlo) & 1) ? -ls : ls;
                const float t0 = v[r0];
                v[r0] = fmaf(c0, v[r1], v[r0]);
                v[r1] = fmaf(c1, t0, v[r1]);
            }
        }
    }
}

template<int L, int P>
__device__ __forceinline__ void gates(float (&v)[64], const float* tanp,
                                      int lane, int wb, int tis, float* sb) {
    do_gate<L, P>(v, tanp[L * NQ + P], lane, wb, tis, sb);
    if constexpr (P + 1 < NQ) gates<L, P + 1>(v, tanp, lane, wb, tis, sb);
}
template<int L>
__device__ __forceinline__ void layers(float (&v)[64], const float* tanp,
                                       int lane, int wb, int tis, float* sb) {
    gates<L, 0>(v, tanp, lane, wb, tis, sb);
    if constexpr (L + 1 < LAYERS) layers<L + 1>(v, tanp, lane, wb, tis, sb);
}

__global__ void __launch_bounds__(TPB, 3) qnn_kernel(
    const float* __restrict__ x,       // [B, 3072]
    const float* __restrict__ angles,  // [8, 12]
    const float* __restrict__ Wm,      // [10, 4096]
    const float* __restrict__ bias,    // [10]
    float* __restrict__ out)           // [B, 10]
{
    __shared__ float s_tan[LAYERS * NQ];
    __shared__ float sb[2 * 64 * 65];          // per-state exchange (33280 B)
    __shared__ float s_ssq[2][2];
    __shared__ float s_out[2][2][NCLASS];

    const int t    = threadIdx.x;
    const int lane = t & 31;
    const int wid  = t >> 5;
    const int st   = wid >> 1;                 // state within CTA (0/1)
    const int wb   = wid & 1;                  // warp bit = physical bit 11
    const int tis  = (wb << 5) | lane;         // thread-in-state 0..63

    if (t < LAYERS * NQ) {
        const int l = t / NQ;
        const int q = t - l * NQ;
        s_tan[l * NQ + (NQ - 1 - q)] = tanf(angles[t]);   // qubit q -> bit 11-q
    }

    const int job = blockIdx.x * 2 + st;

    // global cos product over all 96 gates (per warp, in-register)
    float ctot = cosf(angles[lane]) * cosf(angles[lane + 32]) * cosf(angles[lane + 64]);
    #pragma unroll
    for (int o = 16; o > 0; o >>= 1)
        ctot *= __shfl_xor_sync(0xffffffffu, ctot, o);

    // ---- load: physical slot s = (wb<<11)|(lane<<6)|r = feature index ----
    const int seg = (wb << 11) | (lane << 6);
    float v[64];
    if (seg < FEAT) {
        const float4* x4 = reinterpret_cast<const float4*>(x + (size_t)job * FEAT + seg);
        #pragma unroll
        for (int u = 0; u < 16; u++) {
            const float4 w = x4[u];
            v[4*u+0] = w.x; v[4*u+1] = w.y; v[4*u+2] = w.z; v[4*u+3] = w.w;
        }
    } else {
        #pragma unroll
        for (int r = 0; r < 64; r++) v[r] = 0.0f;
    }

    // half-state sum of squares
    float ssq = 0.0f;
    #pragma unroll
    for (int r = 0; r < 64; r++) ssq = fmaf(v[r], v[r], ssq);
    #pragma unroll
    for (int o = 16; o > 0; o >>= 1) ssq += __shfl_xor_sync(0xffffffffu, ssq, o);
    if (lane == 0) s_ssq[st][wb] = ssq;
    __syncthreads();   // publishes s_tan and s_ssq

    // ---- all 96 gates ----
    layers<0>(v, s_tan, lane, wb, tis, sb + st * 64 * 65);

    // ---- probabilities ----
    #pragma unroll
    for (int r = 0; r < 64; r++) v[r] *= v[r];

    // ---- fold G^8 (j = s ^ (s>>8)): xmask within reg bits 0..3 ----
    const int xmask = ((lane >> 2) & 7) | (wb << 3);
    #pragma unroll
    for (int b = 0; b < 4; b++) {
        const bool sw = (xmask >> b) & 1;
        #pragma unroll
        for (int r0 = 0; r0 < 64; r0++)
            if (!(r0 & (1 << b))) {
                const int r1 = r0 | (1 << b);
                const float a = v[r0], c = v[r1];
                v[r0] = sw ? c : a;
                v[r1] = sw ? a : c;
            }
    }

    // ---- readout partials ----
    #pragma unroll 1
    for (int k = 0; k < NCLASS; k++) {
        const float4* w4 = reinterpret_cast<const float4*>(Wm + (size_t)k * DIM + seg);
        float acc = 0.0f;
        #pragma unroll
        for (int u = 0; u < 16; u++) {
            const float4 w = w4[u];
            acc = fmaf(v[4*u+0], w.x, acc);
            acc = fmaf(v[4*u+1], w.y, acc);
            acc = fmaf(v[4*u+2], w.z, acc);
            acc = fmaf(v[4*u+3], w.w, acc);
        }
        #pragma unroll
        for (int o = 16; o > 0; o >>= 1) acc += __shfl_xor_sync(0xffffffffu, acc, o);
        if (lane == 0) s_out[st][wb][k] = acc;
    }
    __syncthreads();

    if (wb == 0 && lane < NCLASS) {
        const float ssqt  = s_ssq[st][0] + s_ssq[st][1];
        const float scale = (ctot * ctot) / ssqt;
        out[(size_t)job * NCLASS + lane] =
            (s_out[st][0][lane] + s_out[st][1][lane]) * scale + bias[lane];
    }
}

} // namespace

extern "C" void kernel_launch(void* const* d_in, const int* in_sizes, int n_in,
                              void* d_out, int out_size) {
    const float* x      = (const float*)d_in[0];
    const float* angles = (const float*)d_in[1];
    const float* W      = (const float*)d_in[2];
    const float* bias   = (const float*)d_in[3];
    const int batch = in_sizes[0] / FEAT;    // 2048 states
    const int grid  = batch / 2;             // 1024 CTAs (2 states each)
    qnn_kernel<<<grid, TPB>>>(x, angles, W, bias, (float*)d_out);
}

// round 17
// speedup vs baseline: 2.5488x; 1.2342x over previous
#include <cuda_runtime.h>

namespace {

constexpr int NQ     = 12;
constexpr int DIM    = 4096;
constexpr int LAYERS = 8;
constexpr int FEAT   = 3072;
constexpr int NCLASS = 10;
constexpr int TPB    = 64;     // 2 warps per CTA = ONE state per CTA

// ---------------------------------------------------------------------------
// Virtual-permutation algebra (validated: rel_err 1e-6 @ 193us):
// CNOT chain per layer == Gray map j = G i. Data never moves; a gate on
// logical bit p at layer l is an XOR butterfly on physical indices with
//   pair mask  m  = G^{-l} e_p   (lower-triangular: m within bits 0..p)
//   sign mask  sm = (G^T)^l e_p
//   v[s] += (parity(s&sm) ? +t : -t) * v[s^m]      (tan form)
// Final basis map G^8: j = s ^ (s>>8). cos factors + L2 norm folded into
// one epilogue scalar.
//
// Physical layout: s = (warp_bit<<11) | (lane<<6) | reg, 64 floats/thread.
// p<=5: register-only; p=6..10: shfl; p=11 (only): one padded smem swap.
// ---------------------------------------------------------------------------

__host__ __device__ constexpr int gate_m(int l, int p) {   // (G^{-1})^l e_p
    int v = 1 << p;
    for (int it = 0; it < l; it++) {
        int r = 0;
        for (int b = 0; b < 12; b++)
            if ((v >> b) & 1) r ^= (2 << b) - 1;
        v = r;
    }
    return v;
}
__host__ __device__ constexpr int gate_sm(int l, int p) {  // (G^T)^l e_p
    int v = 1 << p;
    for (int it = 0; it < l; it++) {
        int r = 0;
        for (int b = 0; b < 12; b++)
            if ((v >> b) & 1) r ^= ((1 << b) | (1 << (b + 1))) & 0xFFF;
        v = r;
    }
    return v;
}

template<int L, int P>
__device__ __forceinline__ void do_gate(float (&v)[64], float t,
                                        int lane, int wb, int tis, float* sb) {
    constexpr int m      = gate_m(L, P);
    constexpr int regm   = m & 63;
    constexpr int lanem  = (m >> 6) & 31;
    constexpr int wbm    = (m >> 11) & 1;
    constexpr int sm     = gate_sm(L, P);
    constexpr int smlo   = sm & 63;
    constexpr int smlane = (sm >> 6) & 31;
    constexpr int smwb   = (sm >> 11) & 1;

    const float ls = ((__popc(lane & smlane) ^ (wb & smwb)) & 1) ? t : -t;

    if constexpr (wbm == 1) {
        // cross-warp gate (only p = 11): padded smem swap (2-warp barrier)
        #pragma unroll
        for (int r = 0; r < 64; r++) sb[tis * 65 + r] = v[r];
        __syncthreads();
        const int pt = tis ^ 32 ^ lanem;     // partner thread-in-state
        #pragma unroll
        for (int r = 0; r < 64; r++) {
            const float pv = sb[pt * 65 + (r ^ regm)];
            const float c  = (__popc(r & smlo) & 1) ? -ls : ls;
            v[r] = fmaf(c, pv, v[r]);
        }
        __syncthreads();
    } else if constexpr (lanem != 0) {
        #pragma unroll
        for (int r0 = 0; r0 < 64; r0++) {
            const int r1 = r0 ^ regm;
            if (r1 > r0) {
                const float p0 = __shfl_xor_sync(0xffffffffu, v[r1], lanem);
                const float p1 = __shfl_xor_sync(0xffffffffu, v[r0], lanem);
                const float c0 = (__popc(r0 & smlo) & 1) ? -ls : ls;
                const float c1 = (__popc(r1 & smlo) & 1) ? -ls : ls;
                v[r0] = fmaf(c0, p0, v[r0]);
                v[r1] = fmaf(c1, p1, v[r1]);
            } else if (r1 == r0) {
                const float p0 = __shfl_xor_sync(0xffffffffu, v[r0], lanem);
                const float c0 = (__popc(r0 & smlo) & 1) ? -ls : ls;
                v[r0] = fmaf(c0, p0, v[r0]);
            }
        }
    } else {
        #pragma unroll
        for (int r0 = 0; r0 < 64; r0++) {
            const int r1 = r0 ^ regm;
            if (r1 > r0) {
                const float c0 = (__popc(r0 & smlo) & 1) ? -ls : ls;
                const float c1 = (__popc(r1 & smlo) & 1) ? -ls : ls;
                const float t0 = v[r0];
                v[r0] = fmaf(c0, v[r1], v[r0]);
                v[r1] = fmaf(c1, t0, v[r1]);
            }
        }
    }
}

template<int L, int P>
__device__ __forceinline__ void gates(float (&v)[64], const float* tanp,
                                      int lane, int wb, int tis, float* sb) {
    do_gate<L, P>(v, tanp[L * NQ + P], lane, wb, tis, sb);
    if constexpr (P + 1 < NQ) gates<L, P + 1>(v, tanp, lane, wb, tis, sb);
}
template<int L>
__device__ __forceinline__ void layers(float (&v)[64], const float* tanp,
                                       int lane, int wb, int tis, float* sb) {
    gates<L, 0>(v, tanp, lane, wb, tis, sb);
    if constexpr (L + 1 < LAYERS) layers<L + 1>(v, tanp, lane, wb, tis, sb);
}

__global__ void __launch_bounds__(TPB, 8) qnn_kernel(
    const float* __restrict__ x,       // [B, 3072]
    const float* __restrict__ angles,  // [8, 12]
    const float* __restrict__ Wm,      // [10, 4096]
    const float* __restrict__ bias,    // [10]
    float* __restrict__ out)           // [B, 10]
{
    __shared__ float s_tan[LAYERS * NQ];
    __shared__ float sb[64 * 65];              // exchange buffer (16640 B)
    __shared__ float s_ssq[2];
    __shared__ float s_out[2][NCLASS];

    const int t    = threadIdx.x;
    const int lane = t & 31;
    const int wb   = t >> 5;                   // warp bit = physical bit 11
    const int tis  = t;                        // thread-in-state 0..63

    for (int i = t; i < LAYERS * NQ; i += TPB) {
        const int l = i / NQ;
        const int q = i - l * NQ;
        s_tan[l * NQ + (NQ - 1 - q)] = tanf(angles[i]);   // qubit q -> bit 11-q
    }

    const int job = blockIdx.x;

    // global cos product over all 96 gates (per warp, in-register)
    float ctot = cosf(angles[lane]) * cosf(angles[lane + 32]) * cosf(angles[lane + 64]);
    #pragma unroll
    for (int o = 16; o > 0; o >>= 1)
        ctot *= __shfl_xor_sync(0xffffffffu, ctot, o);

    // ---- load: physical slot s = (wb<<11)|(lane<<6)|r = feature index ----
    const int seg = (wb << 11) | (lane << 6);
    float v[64];
    if (seg < FEAT) {
        const float4* x4 = reinterpret_cast<const float4*>(x + (size_t)job * FEAT + seg);
        #pragma unroll
        for (int u = 0; u < 16; u++) {
            const float4 w = x4[u];
            v[4*u+0] = w.x; v[4*u+1] = w.y; v[4*u+2] = w.z; v[4*u+3] = w.w;
        }
    } else {
        #pragma unroll
        for (int r = 0; r < 64; r++) v[r] = 0.0f;
    }

    // half-state sum of squares
    float ssq = 0.0f;
    #pragma unroll
    for (int r = 0; r < 64; r++) ssq = fmaf(v[r], v[r], ssq);
    #pragma unroll
    for (int o = 16; o > 0; o >>= 1) ssq += __shfl_xor_sync(0xffffffffu, ssq, o);
    if (lane == 0) s_ssq[wb] = ssq;
    __syncthreads();   // publishes s_tan and s_ssq

    // ---- all 96 gates ----
    layers<0>(v, s_tan, lane, wb, tis, sb);

    // ---- probabilities ----
    #pragma unroll
    for (int r = 0; r < 64; r++) v[r] *= v[r];

    // ---- fold G^8 (j = s ^ (s>>8)): xmask within reg bits 0..3 ----
    const int xmask = ((lane >> 2) & 7) | (wb << 3);
    #pragma unroll
    for (int b = 0; b < 4; b++) {
        const bool sw = (xmask >> b) & 1;
        #pragma unroll
        for (int r0 = 0; r0 < 64; r0++)
            if (!(r0 & (1 << b))) {
                const int r1 = r0 | (1 << b);
                const float a = v[r0], c = v[r1];
                v[r0] = sw ? c : a;
                v[r1] = sw ? a : c;
            }
    }

    // ---- readout partials ----
    #pragma unroll 1
    for (int k = 0; k < NCLASS; k++) {
        const float4* w4 = reinterpret_cast<const float4*>(Wm + (size_t)k * DIM + seg);
        float acc = 0.0f;
        #pragma unroll
        for (int u = 0; u < 16; u++) {
            const float4 w = w4[u];
            acc = fmaf(v[4*u+0], w.x, acc);
            acc = fmaf(v[4*u+1], w.y, acc);
            acc = fmaf(v[4*u+2], w.z, acc);
            acc = fmaf(v[4*u+3], w.w, acc);
        }
        #pragma unroll
        for (int o = 16; o > 0; o >>= 1) acc += __shfl_xor_sync(0xffffffffu, acc, o);
        if (lane == 0) s_out[wb][k] = acc;
    }
    __syncthreads();

    if (wb == 0 && lane < NCLASS) {
        const float ssqt  = s_ssq[0] + s_ssq[1];
        const float scale = (ctot * ctot) / ssqt;
        out[(size_t)job * NCLASS + lane] =
            (s_out[0][lane] + s_out[1][lane]) * scale + bias[lane];
    }
}

} // namespace

extern "C" void kernel_launch(void* const* d_in, const int* in_sizes, int n_in,
                              void* d_out, int out_size) {
    const float* x      = (const float*)d_in[0];
    const float* angles = (const float*)d_in[1];
    const float* W      = (const float*)d_in[2];
    const float* bias   = (const float*)d_in[3];
    const int batch = in_sizes[0] / FEAT;    // 2048 states
    qnn_kernel<<<batch, TPB>>>(x, angles, W, bias, (float*)d_out);
}